// round 10
// baseline (speedup 1.0000x reference)
#include <cuda_runtime.h>
#include <cstdint>

#define B_SZ   1024
#define HID    512
#define FEAT   32
#define CIN    4
#define KCONV  30
#define STRIDEC 6
#define LIN    924
#define TSTEPS 150
#define KDD    40
#define NSTEPS 10
#define G4     2048          // 4*HID
#define BH     (B_SZ*HID)    // 524288
#define DYN_SMEM 147456      // 2 halves x 2 stages x (A 18KB + B 18KB)

// ---------------- device scratch (static; no allocations) ----------------
__device__ float g_seq[TSTEPS * B_SZ * FEAT];   // conv output (tf32-rounded), [t][b][f]
__device__ float g_W0p[G4 * 544];               // packed+permuted [Wih0|Whh0], tf32-rounded
__device__ float g_W1p[G4 * 1024];              // packed+permuted [Wih1|Whh1]
__device__ float g_b0p[G4];
__device__ float g_b1p[G4];
__device__ float g_state[6 * BH];               // h0[0],h0[1],c0,h1[0],h1[1],c1 (h tf32-rounded, c fp32)
__device__ float g_y[B_SZ * FEAT];              // tf32-rounded decoder output (GEMM input)
__device__ float g_fut[NSTEPS * B_SZ * FEAT];   // full-precision decoder outputs [s][b][f]
__device__ float g_decwT[HID * FEAT];           // dec_w transposed [j][f]

// ---------------- helpers ----------------
__device__ __forceinline__ float to_tf32(float x) {
    float r;
    asm("cvt.rna.tf32.f32 %0, %1;" : "=f"(r) : "f"(x));
    return r;
}
__device__ __forceinline__ uint32_t smem_u32(const void* p) {
    uint32_t a;
    asm("{ .reg .u64 t; cvta.to.shared.u64 t, %1; cvt.u32.u64 %0, t; }" : "=r"(a) : "l"(p));
    return a;
}
__device__ __forceinline__ void mma_tf32(float* d, const unsigned* a, const unsigned* b) {
    asm volatile(
        "mma.sync.aligned.m16n8k8.row.col.f32.tf32.tf32.f32 "
        "{%0,%1,%2,%3}, {%4,%5,%6,%7}, {%8,%9}, {%0,%1,%2,%3};"
        : "+f"(d[0]), "+f"(d[1]), "+f"(d[2]), "+f"(d[3])
        : "r"(a[0]), "r"(a[1]), "r"(a[2]), "r"(a[3]), "r"(b[0]), "r"(b[1]));
}
__device__ __forceinline__ void ldsm_x4(unsigned* r, uint32_t addr) {
    asm volatile("ldmatrix.sync.aligned.m8n8.x4.shared.b16 {%0,%1,%2,%3}, [%4];"
        : "=r"(r[0]), "=r"(r[1]), "=r"(r[2]), "=r"(r[3]) : "r"(addr));
}
#define CP_ASYNC16(sa, gp) \
    asm volatile("cp.async.cg.shared.global [%0], [%1], 16;" :: "r"(sa), "l"(gp))
#define CP_COMMIT() asm volatile("cp.async.commit_group;" ::: "memory")
#define CP_WAIT1()  asm volatile("cp.async.wait_group 1;" ::: "memory")
#define CP_WAIT0()  asm volatile("cp.async.wait_group 0;" ::: "memory")
#define BARH(h) asm volatile("bar.sync %0, 128;" :: "r"(1 + (h)) : "memory")

// ---------------- fused setup: zero state + pack weights (one launch) ----------------
__global__ void setup_kernel(const float* __restrict__ Wih0, const float* __restrict__ Whh0,
                             const float* __restrict__ bih0, const float* __restrict__ bhh0,
                             const float* __restrict__ Wih1, const float* __restrict__ Whh1,
                             const float* __restrict__ bih1, const float* __restrict__ bhh1,
                             const float* __restrict__ dec_w) {
    long i = (long)blockIdx.x * blockDim.x + threadIdx.x;
    if (i < 6L * BH) { g_state[i] = 0.f; return; }
    long j = i - 6L * BH;
    if (j < (long)G4 * 544) {
        int p = (int)(j / 544), k = (int)(j - (long)p * 544);
        int blk = p >> 7, gt = (p >> 5) & 3, u = p & 31;
        int g = gt * HID + blk * 32 + u;
        float v = (k < FEAT) ? Wih0[g * FEAT + k] : Whh0[g * HID + (k - FEAT)];
        g_W0p[j] = to_tf32(v);
        if (k == 0) g_b0p[p] = bih0[g] + bhh0[g];
        return;
    }
    long k2 = j - (long)G4 * 544;
    if (k2 < (long)G4 * 1024) {
        int p = (int)(k2 >> 10), k = (int)(k2 & 1023);
        int blk = p >> 7, gt = (p >> 5) & 3, u = p & 31;
        int g = gt * HID + blk * 32 + u;
        float v = (k < HID) ? Wih1[g * HID + k] : Whh1[g * HID + (k - HID)];
        g_W1p[k2] = to_tf32(v);
        if (k == 0) g_b1p[p] = bih1[g] + bhh1[g];
        return;
    }
    long k3 = k2 - (long)G4 * 1024;
    if (k3 < (long)HID * FEAT) {
        int jj = (int)(k3 >> 5), f = (int)(k3 & 31);
        g_decwT[jj * FEAT + f] = dec_w[f * HID + jj];
    }
}
#define SETUP_ITEMS (6L * BH + (long)G4 * 544 + (long)G4 * 1024 + (long)HID * FEAT)

// ---------------- encoder conv: [B,4,924] -> seq[t][b][f], relu, tf32-rounded ------
__global__ void conv_kernel(const float* __restrict__ x,
                            const float* __restrict__ w,
                            const float* __restrict__ bias) {
    __shared__ float xs[CIN * LIN];
    __shared__ float ws[FEAT * CIN * KCONV];
    __shared__ float bs[FEAT];
    int b = blockIdx.x;
    for (int i = threadIdx.x; i < CIN * LIN; i += blockDim.x) xs[i] = x[b * CIN * LIN + i];
    for (int i = threadIdx.x; i < FEAT * CIN * KCONV; i += blockDim.x) ws[i] = w[i];
    if (threadIdx.x < FEAT) bs[threadIdx.x] = bias[threadIdx.x];
    __syncthreads();
    for (int o = threadIdx.x; o < FEAT * TSTEPS; o += blockDim.x) {
        int f = o / TSTEPS, t = o % TSTEPS;
        float acc = bs[f];
        #pragma unroll
        for (int c = 0; c < CIN; c++) {
            const float* xr = xs + c * LIN + t * STRIDEC;
            const float* wr = ws + (f * CIN + c) * KCONV;
            #pragma unroll
            for (int k = 0; k < KCONV; k++) acc += xr[k] * wr[k];
        }
        g_seq[(t * B_SZ + b) * FEAT + f] = to_tf32(fmaxf(acc, 0.f));
    }
}

// ---------------- split-K fused LSTM step ----------------
// CTA tile 128x128 (bM batch, bN packed-gates). 8 warps: half = warp>>2 owns a
// disjoint k-tile subset (kt ≡ half mod 2); per half a 2x2 grid of 64x64 warp
// tiles. cp.async double buffer per half, ldmatrix fragment loads (4x fewer
// shared-mem instructions vs scalar LDS). Halves reduce partials in smem,
// then fused LSTM cell update.
__global__ void __launch_bounds__(256, 1)
lstm_step_kernel(const float* __restrict__ x1, int w1,
                 const float* __restrict__ h_in, int K,
                 const float* __restrict__ Wp, const float* __restrict__ bp,
                 float* __restrict__ c_state, float* __restrict__ h_out) {
    extern __shared__ float smem[];
    const int tid  = threadIdx.x;
    const int lane = tid & 31;
    const int warp = tid >> 5;
    const int half = warp >> 2;
    const int wl   = warp & 3;
    const int wm   = wl >> 1;      // 0..1 : 64-row band
    const int wn   = wl & 1;       // 0..1 : 64-col band
    const int t128 = tid & 127;
    const int bN = blockIdx.x, bM = blockIdx.y;
    const int NT = K >> 5;

    float* hbase = smem + half * 18432;    // per-half area: 2 stages x 9216 floats

    // ldmatrix per-thread row/col offsets (see fragment mapping note above)
    const int tA  = lane & 7;
    const int rowA = tA + ((lane >> 3) & 1) * 8;
    const int colA = (lane >> 4) * 4;
    const int rowB = tA + (lane >> 4) * 8;
    const int colB = ((lane >> 3) & 1) * 4;

    float acc[4][8][4];
    #pragma unroll
    for (int a = 0; a < 4; a++)
        #pragma unroll
        for (int b = 0; b < 8; b++)
            #pragma unroll
            for (int c = 0; c < 4; c++) acc[a][b][c] = 0.f;

    auto prefetch = [&](int kt, int s) {
        float* As = hbase + s * 9216;
        float* Bs = As + 4608;
        uint32_t a_s = smem_u32(As), b_s = smem_u32(Bs);
        const int k0 = kt * 32;
        #pragma unroll
        for (int i = 0; i < 8; i++) {
            int chunk = t128 + i * 128;
            int row = chunk >> 3, c4 = (chunk & 7) * 4;
            const float* src = (k0 < w1)
                ? x1 + (size_t)(bM * 128 + row) * w1 + k0 + c4
                : h_in + (size_t)(bM * 128 + row) * HID + (k0 - w1) + c4;
            CP_ASYNC16(a_s + (uint32_t)(row * 36 + c4) * 4u, src);
        }
        #pragma unroll
        for (int i = 0; i < 8; i++) {
            int chunk = t128 + i * 128;
            int row = chunk >> 3, c4 = (chunk & 7) * 4;
            CP_ASYNC16(b_s + (uint32_t)(row * 36 + c4) * 4u,
                       Wp + (size_t)(bN * 128 + row) * K + k0 + c4);
        }
    };

    auto compute = [&](int s) {
        const float* As = hbase + s * 9216;
        const float* Bs = As + 4608;
        const uint32_t a_base = smem_u32(As)
            + (uint32_t)(((wm * 64 + rowA) * 36 + colA) * 4);
        const uint32_t b_base = smem_u32(Bs)
            + (uint32_t)(((wn * 64 + rowB) * 36 + colB) * 4);
        #pragma unroll
        for (int kk = 0; kk < 4; kk++) {
            unsigned af[4][4];
            #pragma unroll
            for (int mt = 0; mt < 4; mt++)
                ldsm_x4(af[mt], a_base + (uint32_t)((mt * 16 * 36 + kk * 8) * 4));
            unsigned bq[4][4];
            #pragma unroll
            for (int ntp = 0; ntp < 4; ntp++)
                ldsm_x4(bq[ntp], b_base + (uint32_t)((ntp * 16 * 36 + kk * 8) * 4));
            #pragma unroll
            for (int mt = 0; mt < 4; mt++)
                #pragma unroll
                for (int ntp = 0; ntp < 4; ntp++) {
                    mma_tf32(acc[mt][2 * ntp],     af[mt], &bq[ntp][0]);
                    mma_tf32(acc[mt][2 * ntp + 1], af[mt], &bq[ntp][2]);
                }
        }
    };

    // per-half pipelined mainloop over k-tiles kt = half, half+2, ...
    prefetch(half, 0);
    CP_COMMIT();
    if (half + 2 < NT) prefetch(half + 2, 1);
    CP_COMMIT();
    int buf = 0;
    for (int kt = half; kt < NT; kt += 2) {
        if (kt + 2 < NT) { CP_WAIT1(); } else { CP_WAIT0(); }
        BARH(half);
        compute(buf);
        BARH(half);
        if (kt + 4 < NT) prefetch(kt + 4, buf);
        CP_COMMIT();
        buf ^= 1;
    }

    // ---- cross-half reduction into gs (stride 132), then cell update ----
    __syncthreads();
    float* gs = smem;
    if (half == 1) {
        #pragma unroll
        for (int mt = 0; mt < 4; mt++)
            #pragma unroll
            for (int nt = 0; nt < 8; nt++) {
                int r0 = wm * 64 + mt * 16 + (lane >> 2);
                int c0 = wn * 64 + nt * 8 + (lane & 3) * 2;
                gs[r0 * 132 + c0]           = acc[mt][nt][0];
                gs[r0 * 132 + c0 + 1]       = acc[mt][nt][1];
                gs[(r0 + 8) * 132 + c0]     = acc[mt][nt][2];
                gs[(r0 + 8) * 132 + c0 + 1] = acc[mt][nt][3];
            }
    }
    __syncthreads();
    if (half == 0) {
        #pragma unroll
        for (int mt = 0; mt < 4; mt++)
            #pragma unroll
            for (int nt = 0; nt < 8; nt++) {
                int r0 = wm * 64 + mt * 16 + (lane >> 2);
                int c0 = wn * 64 + nt * 8 + (lane & 3) * 2;
                gs[r0 * 132 + c0]           += acc[mt][nt][0];
                gs[r0 * 132 + c0 + 1]       += acc[mt][nt][1];
                gs[(r0 + 8) * 132 + c0]     += acc[mt][nt][2];
                gs[(r0 + 8) * 132 + c0 + 1] += acc[mt][nt][3];
            }
    }
    __syncthreads();

    {
        int u = tid & 31;
        int brow0 = tid >> 5;
        float bi  = bp[bN * 128 + u];
        float bf_ = bp[bN * 128 + 32 + u];
        float bg  = bp[bN * 128 + 64 + u];
        float bo  = bp[bN * 128 + 96 + u];
        int j = bN * 32 + u;   // hidden unit index
        #pragma unroll
        for (int i = 0; i < 16; i++) {
            int bl = brow0 + i * 8;
            int bglob = bM * 128 + bl;
            float gi = gs[bl * 132 + u] + bi;
            float gf = gs[bl * 132 + 32 + u] + bf_;
            float gg = gs[bl * 132 + 64 + u] + bg;
            float go = gs[bl * 132 + 96 + u] + bo;
            float iv = 1.f / (1.f + __expf(-gi));
            float fv = 1.f / (1.f + __expf(-gf));
            float gv = tanhf(gg);
            float ov = 1.f / (1.f + __expf(-go));
            int idx = bglob * HID + j;
            float cn = fv * c_state[idx] + iv * gv;
            c_state[idx] = cn;
            h_out[idx] = to_tf32(ov * tanhf(cn));   // GEMM operand: pre-rounded
        }
    }
}

// ---------------- decoder projection: y = h @ dec_w^T + dec_b ----------------
__global__ void dec_out_kernel(const float* __restrict__ h, float* __restrict__ y,
                               const float* __restrict__ dec_b, int slot) {
    int g = blockIdx.x * blockDim.x + threadIdx.x;  // 32768
    int b = g >> 5, f = g & 31;
    float acc = dec_b[f];
    const float* hr = h + b * HID;
    #pragma unroll 8
    for (int j = 0; j < HID; j++) acc += hr[j] * g_decwT[j * FEAT + f];
    y[b * FEAT + f] = to_tf32(acc);                 // GEMM operand: pre-rounded
    if (slot >= 0) g_fut[(slot * B_SZ + b) * FEAT + f] = acc;  // full precision for output
}

// ---------------- conv transpose: fut[b,f,10] * w[f,1,40] -> out[b,1,49] ----------------
__global__ void deconv_kernel(const float* __restrict__ dw, float* __restrict__ out) {
    __shared__ float futb[NSTEPS * FEAT];
    __shared__ float dws[FEAT * KDD];
    int b = blockIdx.x;
    for (int i = threadIdx.x; i < NSTEPS * FEAT; i += blockDim.x) {
        int t = i >> 5, f = i & 31;
        futb[i] = g_fut[(t * B_SZ + b) * FEAT + f];
    }
    for (int i = threadIdx.x; i < FEAT * KDD; i += blockDim.x) dws[i] = dw[i];
    __syncthreads();
    int jj = threadIdx.x;
    if (jj < NSTEPS + KDD - 1) {
        float acc = 0.f;
        #pragma unroll
        for (int t = 0; t < NSTEPS; t++) {
            int k = jj - t;
            if (k >= 0 && k < KDD) {
                #pragma unroll
                for (int f = 0; f < FEAT; f++) acc += futb[t * FEAT + f] * dws[f * KDD + k];
            }
        }
        out[b * (NSTEPS + KDD - 1) + jj] = acc;
    }
}

// ---------------- host ----------------
extern "C" void kernel_launch(void* const* d_in, const int* in_sizes, int n_in,
                              void* d_out, int out_size) {
    const float* x       = (const float*)d_in[0];
    const float* conv_w  = (const float*)d_in[1];
    const float* conv_b  = (const float*)d_in[2];
    const float* Wih0    = (const float*)d_in[3];
    const float* Whh0    = (const float*)d_in[4];
    const float* bih0    = (const float*)d_in[5];
    const float* bhh0    = (const float*)d_in[6];
    const float* Wih1    = (const float*)d_in[7];
    const float* Whh1    = (const float*)d_in[8];
    const float* bih1    = (const float*)d_in[9];
    const float* bhh1    = (const float*)d_in[10];
    const float* dec_w   = (const float*)d_in[11];
    const float* dec_b   = (const float*)d_in[12];
    const float* deconvw = (const float*)d_in[13];

    cudaFuncSetAttribute(lstm_step_kernel,
                         cudaFuncAttributeMaxDynamicSharedMemorySize, DYN_SMEM);

    float *seq, *state, *yb, *W0p, *W1p, *b0p, *b1p;
    cudaGetSymbolAddress((void**)&seq,   g_seq);
    cudaGetSymbolAddress((void**)&state, g_state);
    cudaGetSymbolAddress((void**)&yb,    g_y);
    cudaGetSymbolAddress((void**)&W0p,   g_W0p);
    cudaGetSymbolAddress((void**)&W1p,   g_W1p);
    cudaGetSymbolAddress((void**)&b0p,   g_b0p);
    cudaGetSymbolAddress((void**)&b1p,   g_b1p);

    float* h0[2] = { state,          state + BH };
    float* c0    =   state + 2 * BH;
    float* h1[2] = { state + 3 * BH, state + 4 * BH };
    float* c1    =   state + 5 * BH;

    // launch order puts the K=1024 step at harness index 3 (= ncu -s 5 window)
    setup_kernel<<<(int)((SETUP_ITEMS + 255) / 256), 256>>>(Wih0, Whh0, bih0, bhh0,
                                                            Wih1, Whh1, bih1, bhh1, dec_w);
    conv_kernel<<<B_SZ, 256>>>(x, conv_w, conv_b);

    dim3 sgrid(16, 8), sblk(256);
    for (int t = 0; t < TSTEPS; t++) {
        lstm_step_kernel<<<sgrid, sblk, DYN_SMEM>>>(seq + (size_t)t * B_SZ * FEAT, FEAT,
                                                    h0[t & 1], 544, W0p, b0p, c0, h0[(t + 1) & 1]);
        lstm_step_kernel<<<sgrid, sblk, DYN_SMEM>>>(h0[(t + 1) & 1], HID,
                                                    h1[t & 1], 1024, W1p, b1p, c1, h1[(t + 1) & 1]);
    }

    // y0 = h1_final @ dec_w^T + dec_b   (TSTEPS even -> final parity 0)
    dec_out_kernel<<<128, 256>>>(h1[0], yb, dec_b, -1);

    for (int s = 0; s < NSTEPS; s++) {
        lstm_step_kernel<<<sgrid, sblk, DYN_SMEM>>>(yb, FEAT,
                                                    h0[s & 1], 544, W0p, b0p, c0, h0[(s + 1) & 1]);
        lstm_step_kernel<<<sgrid, sblk, DYN_SMEM>>>(h0[(s + 1) & 1], HID,
                                                    h1[s & 1], 1024, W1p, b1p, c1, h1[(s + 1) & 1]);
        dec_out_kernel<<<128, 256>>>(h1[(s + 1) & 1], yb, dec_b, s);
    }

    deconv_kernel<<<B_SZ, 64>>>(deconvw, (float*)d_out);
}

// round 11
// speedup vs baseline: 1.2888x; 1.2888x over previous
#include <cuda_runtime.h>
#include <cuda_fp16.h>
#include <cstdint>

#define B_SZ   1024
#define HID    512
#define FEAT   32
#define CIN    4
#define KCONV  30
#define STRIDEC 6
#define LIN    924
#define TSTEPS 150
#define KDD    40
#define NSTEPS 10
#define G4     2048          // 4*HID
#define BH     (B_SZ*HID)    // 524288

// f16 tiles: row stride 40 halves (80B, conflict-free ldmatrix phases)
#define TSTRIDE 40
#define A_HALVES (128 * TSTRIDE)            // 5120
#define STAGE_HALVES (2 * A_HALVES)         // A + B = 10240
#define DYN_SMEM (2 * 2 * STAGE_HALVES * 2) // 2 halves x 2 stages x halves x 2B = 81920

// ---------------- device scratch (static; no allocations) ----------------
__device__ __half g_seq[TSTEPS * B_SZ * FEAT];  // conv output (fp16), [t][b][f]
__device__ __half g_W0h[G4 * 544];              // packed+permuted [Wih0|Whh0], fp16
__device__ __half g_W1h[G4 * 1024];             // packed+permuted [Wih1|Whh1], fp16
__device__ float  g_b0p[G4];
__device__ float  g_b1p[G4];
__device__ __half g_h[4 * BH];                  // h0[0],h0[1],h1[0],h1[1] (fp16)
__device__ float  g_c[2 * BH];                  // c0, c1 (fp32)
__device__ __half g_y[B_SZ * FEAT];             // decoder output (GEMM operand, fp16)
__device__ float  g_fut[NSTEPS * B_SZ * FEAT];  // full-precision decoder outputs [s][b][f]
__device__ float  g_decwT[HID * FEAT];          // dec_w transposed [j][f]

// ---------------- helpers ----------------
__device__ __forceinline__ uint32_t smem_u32(const void* p) {
    uint32_t a;
    asm("{ .reg .u64 t; cvta.to.shared.u64 t, %1; cvt.u32.u64 %0, t; }" : "=r"(a) : "l"(p));
    return a;
}
__device__ __forceinline__ void mma_f16(float* d, const unsigned* a, const unsigned* b) {
    asm volatile(
        "mma.sync.aligned.m16n8k16.row.col.f32.f16.f16.f32 "
        "{%0,%1,%2,%3}, {%4,%5,%6,%7}, {%8,%9}, {%0,%1,%2,%3};"
        : "+f"(d[0]), "+f"(d[1]), "+f"(d[2]), "+f"(d[3])
        : "r"(a[0]), "r"(a[1]), "r"(a[2]), "r"(a[3]), "r"(b[0]), "r"(b[1]));
}
__device__ __forceinline__ void ldsm_x4(unsigned* r, uint32_t addr) {
    asm volatile("ldmatrix.sync.aligned.m8n8.x4.shared.b16 {%0,%1,%2,%3}, [%4];"
        : "=r"(r[0]), "=r"(r[1]), "=r"(r[2]), "=r"(r[3]) : "r"(addr));
}
#define CP_ASYNC16(sa, gp) \
    asm volatile("cp.async.cg.shared.global [%0], [%1], 16;" :: "r"(sa), "l"(gp))
#define CP_COMMIT() asm volatile("cp.async.commit_group;" ::: "memory")
#define CP_WAIT1()  asm volatile("cp.async.wait_group 1;" ::: "memory")
#define CP_WAIT0()  asm volatile("cp.async.wait_group 0;" ::: "memory")
#define BARH(h) asm volatile("bar.sync %0, 128;" :: "r"(1 + (h)) : "memory")

// ---------------- fused setup: zero state + pack weights (one launch) ----------------
__global__ void setup_kernel(const float* __restrict__ Wih0, const float* __restrict__ Whh0,
                             const float* __restrict__ bih0, const float* __restrict__ bhh0,
                             const float* __restrict__ Wih1, const float* __restrict__ Whh1,
                             const float* __restrict__ bih1, const float* __restrict__ bhh1,
                             const float* __restrict__ dec_w) {
    long i = (long)blockIdx.x * blockDim.x + threadIdx.x;
    if (i < 2L * BH) { g_c[i] = 0.f; return; }
    long j = i - 2L * BH;
    if (j < 4L * BH) { g_h[j] = __float2half(0.f); return; }
    long j2 = j - 4L * BH;
    if (j2 < (long)G4 * 544) {
        int p = (int)(j2 / 544), k = (int)(j2 - (long)p * 544);
        int blk = p >> 7, gt = (p >> 5) & 3, u = p & 31;
        int g = gt * HID + blk * 32 + u;
        float v = (k < FEAT) ? Wih0[g * FEAT + k] : Whh0[g * HID + (k - FEAT)];
        g_W0h[j2] = __float2half(v);
        if (k == 0) g_b0p[p] = bih0[g] + bhh0[g];
        return;
    }
    long k2 = j2 - (long)G4 * 544;
    if (k2 < (long)G4 * 1024) {
        int p = (int)(k2 >> 10), k = (int)(k2 & 1023);
        int blk = p >> 7, gt = (p >> 5) & 3, u = p & 31;
        int g = gt * HID + blk * 32 + u;
        float v = (k < HID) ? Wih1[g * HID + k] : Whh1[g * HID + (k - HID)];
        g_W1h[k2] = __float2half(v);
        if (k == 0) g_b1p[p] = bih1[g] + bhh1[g];
        return;
    }
    long k3 = k2 - (long)G4 * 1024;
    if (k3 < (long)HID * FEAT) {
        int jj = (int)(k3 >> 5), f = (int)(k3 & 31);
        g_decwT[jj * FEAT + f] = dec_w[f * HID + jj];
    }
}
#define SETUP_ITEMS (2L * BH + 4L * BH + (long)G4 * 544 + (long)G4 * 1024 + (long)HID * FEAT)

// ---------------- encoder conv: [B,4,924] -> seq[t][b][f], relu, fp16 ------
__global__ void conv_kernel(const float* __restrict__ x,
                            const float* __restrict__ w,
                            const float* __restrict__ bias) {
    __shared__ float xs[CIN * LIN];
    __shared__ float ws[FEAT * CIN * KCONV];
    __shared__ float bs[FEAT];
    int b = blockIdx.x;
    for (int i = threadIdx.x; i < CIN * LIN; i += blockDim.x) xs[i] = x[b * CIN * LIN + i];
    for (int i = threadIdx.x; i < FEAT * CIN * KCONV; i += blockDim.x) ws[i] = w[i];
    if (threadIdx.x < FEAT) bs[threadIdx.x] = bias[threadIdx.x];
    __syncthreads();
    for (int o = threadIdx.x; o < FEAT * TSTEPS; o += blockDim.x) {
        int f = o / TSTEPS, t = o % TSTEPS;
        float acc = bs[f];
        #pragma unroll
        for (int c = 0; c < CIN; c++) {
            const float* xr = xs + c * LIN + t * STRIDEC;
            const float* wr = ws + (f * CIN + c) * KCONV;
            #pragma unroll
            for (int k = 0; k < KCONV; k++) acc += xr[k] * wr[k];
        }
        g_seq[(t * B_SZ + b) * FEAT + f] = __float2half(fmaxf(acc, 0.f));
    }
}

// ---------------- split-K fused LSTM step (fp16 mma m16n8k16) ----------------
// CTA tile 128x128 (bM batch, bN packed-gates). 8 warps: half = warp>>2 owns a
// disjoint k-tile subset (kt ≡ half mod 2); per half a 2x2 grid of 64x64 warp
// tiles. cp.async double buffer per half, ldmatrix b16 fragment loads.
// Halves reduce fp32 partials in smem, then fused LSTM cell update.
__global__ void __launch_bounds__(256, 1)
lstm_step_kernel(const __half* __restrict__ x1, int w1,
                 const __half* __restrict__ h_in, int K,
                 const __half* __restrict__ Wp, const float* __restrict__ bp,
                 float* __restrict__ c_state, __half* __restrict__ h_out) {
    extern __shared__ __half smem[];
    const int tid  = threadIdx.x;
    const int lane = tid & 31;
    const int warp = tid >> 5;
    const int half = warp >> 2;
    const int wl   = warp & 3;
    const int wm   = wl >> 1;      // 0..1 : 64-row band
    const int wn   = wl & 1;       // 0..1 : 64-col band
    const int t128 = tid & 127;
    const int bN = blockIdx.x, bM = blockIdx.y;
    const int NT = K >> 5;

    __half* hbase = smem + half * (2 * STAGE_HALVES);   // per-half: 2 stages

    // ldmatrix lane addressing (b16, x4):
    // A tile (m16 x k16 quads): groups: +0/+8 rows, +0/+8 k-halves
    const int rowA = (lane & 7) + ((lane >> 3) & 1) * 8;
    const int colA = (lane >> 4) * 8;
    // B tile (n16 x k16 quads): groups: n+0..7/k0, n+0..7/k+8, n+8..15/k0, n+8..15/k+8
    const int rowB = (lane & 7) + ((lane >> 4) ? 8 : 0);
    const int colB = ((lane >> 3) & 1) * 8;

    float acc[4][8][4];
    #pragma unroll
    for (int a = 0; a < 4; a++)
        #pragma unroll
        for (int b = 0; b < 8; b++)
            #pragma unroll
            for (int c = 0; c < 4; c++) acc[a][b][c] = 0.f;

    auto prefetch = [&](int kt, int s) {
        __half* As = hbase + s * STAGE_HALVES;
        __half* Bs = As + A_HALVES;
        uint32_t a_s = smem_u32(As), b_s = smem_u32(Bs);
        const int k0 = kt * 32;
        // A: 128 rows x 32 halves = 512 x 16B chunks
        #pragma unroll
        for (int i = 0; i < 4; i++) {
            int chunk = t128 + i * 128;
            int row = chunk >> 2, c8 = (chunk & 3) * 8;
            const __half* src = (k0 < w1)
                ? x1 + (size_t)(bM * 128 + row) * w1 + k0 + c8
                : h_in + (size_t)(bM * 128 + row) * HID + (k0 - w1) + c8;
            CP_ASYNC16(a_s + (uint32_t)(row * TSTRIDE + c8) * 2u, src);
        }
        // B: 128 rows x 32 halves
        #pragma unroll
        for (int i = 0; i < 4; i++) {
            int chunk = t128 + i * 128;
            int row = chunk >> 2, c8 = (chunk & 3) * 8;
            CP_ASYNC16(b_s + (uint32_t)(row * TSTRIDE + c8) * 2u,
                       Wp + (size_t)(bN * 128 + row) * K + k0 + c8);
        }
    };

    auto compute = [&](int s) {
        const __half* As = hbase + s * STAGE_HALVES;
        const __half* Bs = As + A_HALVES;
        const uint32_t a_base = smem_u32(As)
            + (uint32_t)(((wm * 64 + rowA) * TSTRIDE + colA) * 2);
        const uint32_t b_base = smem_u32(Bs)
            + (uint32_t)(((wn * 64 + rowB) * TSTRIDE + colB) * 2);
        #pragma unroll
        for (int kk = 0; kk < 2; kk++) {   // two k16 slices per 32-K tile
            unsigned af[4][4];
            #pragma unroll
            for (int mt = 0; mt < 4; mt++)
                ldsm_x4(af[mt], a_base + (uint32_t)((mt * 16 * TSTRIDE + kk * 16) * 2));
            unsigned bq[4][4];
            #pragma unroll
            for (int bi = 0; bi < 4; bi++)   // 4 x (16 n-rows)
                ldsm_x4(bq[bi], b_base + (uint32_t)((bi * 16 * TSTRIDE + kk * 16) * 2));
            #pragma unroll
            for (int mt = 0; mt < 4; mt++)
                #pragma unroll
                for (int bi = 0; bi < 4; bi++) {
                    mma_f16(acc[mt][2 * bi],     af[mt], &bq[bi][0]);
                    mma_f16(acc[mt][2 * bi + 1], af[mt], &bq[bi][2]);
                }
        }
    };

    // per-half pipelined mainloop over k-tiles kt = half, half+2, ...
    prefetch(half, 0);
    CP_COMMIT();
    if (half + 2 < NT) prefetch(half + 2, 1);
    CP_COMMIT();
    int buf = 0;
    for (int kt = half; kt < NT; kt += 2) {
        if (kt + 2 < NT) { CP_WAIT1(); } else { CP_WAIT0(); }
        BARH(half);
        compute(buf);
        BARH(half);
        if (kt + 4 < NT) prefetch(kt + 4, buf);
        CP_COMMIT();
        buf ^= 1;
    }

    // ---- cross-half reduction into gs (fp32, stride 132), then cell update ----
    __syncthreads();
    float* gs = (float*)smem;
    if (half == 1) {
        #pragma unroll
        for (int mt = 0; mt < 4; mt++)
            #pragma unroll
            for (int nt = 0; nt < 8; nt++) {
                int r0 = wm * 64 + mt * 16 + (lane >> 2);
                int c0 = wn * 64 + nt * 8 + (lane & 3) * 2;
                gs[r0 * 132 + c0]           = acc[mt][nt][0];
                gs[r0 * 132 + c0 + 1]       = acc[mt][nt][1];
                gs[(r0 + 8) * 132 + c0]     = acc[mt][nt][2];
                gs[(r0 + 8) * 132 + c0 + 1] = acc[mt][nt][3];
            }
    }
    __syncthreads();
    if (half == 0) {
        #pragma unroll
        for (int mt = 0; mt < 4; mt++)
            #pragma unroll
            for (int nt = 0; nt < 8; nt++) {
                int r0 = wm * 64 + mt * 16 + (lane >> 2);
                int c0 = wn * 64 + nt * 8 + (lane & 3) * 2;
                gs[r0 * 132 + c0]           += acc[mt][nt][0];
                gs[r0 * 132 + c0 + 1]       += acc[mt][nt][1];
                gs[(r0 + 8) * 132 + c0]     += acc[mt][nt][2];
                gs[(r0 + 8) * 132 + c0 + 1] += acc[mt][nt][3];
            }
    }
    __syncthreads();

    {
        int u = tid & 31;
        int brow0 = tid >> 5;
        float bi  = bp[bN * 128 + u];
        float bf_ = bp[bN * 128 + 32 + u];
        float bg  = bp[bN * 128 + 64 + u];
        float bo  = bp[bN * 128 + 96 + u];
        int j = bN * 32 + u;   // hidden unit index
        #pragma unroll
        for (int i = 0; i < 16; i++) {
            int bl = brow0 + i * 8;
            int bglob = bM * 128 + bl;
            float gi = gs[bl * 132 + u] + bi;
            float gf = gs[bl * 132 + 32 + u] + bf_;
            float gg = gs[bl * 132 + 64 + u] + bg;
            float go = gs[bl * 132 + 96 + u] + bo;
            float iv = 1.f / (1.f + __expf(-gi));
            float fv = 1.f / (1.f + __expf(-gf));
            float gv = tanhf(gg);
            float ov = 1.f / (1.f + __expf(-go));
            int idx = bglob * HID + j;
            float cn = fv * c_state[idx] + iv * gv;
            c_state[idx] = cn;
            h_out[idx] = __float2half(ov * tanhf(cn));   // GEMM operand (fp16)
        }
    }
}

// ---------------- decoder projection: y = h @ dec_w^T + dec_b ----------------
__global__ void dec_out_kernel(const __half* __restrict__ h, __half* __restrict__ y,
                               const float* __restrict__ dec_b, int slot) {
    int g = blockIdx.x * blockDim.x + threadIdx.x;  // 32768
    int b = g >> 5, f = g & 31;
    float acc = dec_b[f];
    const __half* hr = h + (size_t)b * HID;
    #pragma unroll 8
    for (int j = 0; j < HID; j++) acc += __half2float(hr[j]) * g_decwT[j * FEAT + f];
    y[b * FEAT + f] = __float2half(acc);            // GEMM operand (fp16)
    if (slot >= 0) g_fut[(slot * B_SZ + b) * FEAT + f] = acc;  // full precision for output
}

// ---------------- conv transpose: fut[b,f,10] * w[f,1,40] -> out[b,1,49] ----------------
__global__ void deconv_kernel(const float* __restrict__ dw, float* __restrict__ out) {
    __shared__ float futb[NSTEPS * FEAT];
    __shared__ float dws[FEAT * KDD];
    int b = blockIdx.x;
    for (int i = threadIdx.x; i < NSTEPS * FEAT; i += blockDim.x) {
        int t = i >> 5, f = i & 31;
        futb[i] = g_fut[(t * B_SZ + b) * FEAT + f];
    }
    for (int i = threadIdx.x; i < FEAT * KDD; i += blockDim.x) dws[i] = dw[i];
    __syncthreads();
    int jj = threadIdx.x;
    if (jj < NSTEPS + KDD - 1) {
        float acc = 0.f;
        #pragma unroll
        for (int t = 0; t < NSTEPS; t++) {
            int k = jj - t;
            if (k >= 0 && k < KDD) {
                #pragma unroll
                for (int f = 0; f < FEAT; f++) acc += futb[t * FEAT + f] * dws[f * KDD + k];
            }
        }
        out[b * (NSTEPS + KDD - 1) + jj] = acc;
    }
}

// ---------------- host ----------------
extern "C" void kernel_launch(void* const* d_in, const int* in_sizes, int n_in,
                              void* d_out, int out_size) {
    const float* x       = (const float*)d_in[0];
    const float* conv_w  = (const float*)d_in[1];
    const float* conv_b  = (const float*)d_in[2];
    const float* Wih0    = (const float*)d_in[3];
    const float* Whh0    = (const float*)d_in[4];
    const float* bih0    = (const float*)d_in[5];
    const float* bhh0    = (const float*)d_in[6];
    const float* Wih1    = (const float*)d_in[7];
    const float* Whh1    = (const float*)d_in[8];
    const float* bih1    = (const float*)d_in[9];
    const float* bhh1    = (const float*)d_in[10];
    const float* dec_w   = (const float*)d_in[11];
    const float* dec_b   = (const float*)d_in[12];
    const float* deconvw = (const float*)d_in[13];

    cudaFuncSetAttribute(lstm_step_kernel,
                         cudaFuncAttributeMaxDynamicSharedMemorySize, DYN_SMEM);

    __half *seq, *hbuf, *yb, *W0h, *W1h;
    float *cbuf, *b0p, *b1p;
    cudaGetSymbolAddress((void**)&seq,  g_seq);
    cudaGetSymbolAddress((void**)&hbuf, g_h);
    cudaGetSymbolAddress((void**)&cbuf, g_c);
    cudaGetSymbolAddress((void**)&yb,   g_y);
    cudaGetSymbolAddress((void**)&W0h,  g_W0h);
    cudaGetSymbolAddress((void**)&W1h,  g_W1h);
    cudaGetSymbolAddress((void**)&b0p,  g_b0p);
    cudaGetSymbolAddress((void**)&b1p,  g_b1p);

    __half* h0[2] = { hbuf,          hbuf + BH };
    __half* h1[2] = { hbuf + 2 * BH, hbuf + 3 * BH };
    float*  c0    = cbuf;
    float*  c1    = cbuf + BH;

    // launch order keeps the K=1024 step at harness index 3 (= ncu -s 5 window)
    setup_kernel<<<(int)((SETUP_ITEMS + 255) / 256), 256>>>(Wih0, Whh0, bih0, bhh0,
                                                            Wih1, Whh1, bih1, bhh1, dec_w);
    conv_kernel<<<B_SZ, 256>>>(x, conv_w, conv_b);

    dim3 sgrid(16, 8), sblk(256);
    for (int t = 0; t < TSTEPS; t++) {
        lstm_step_kernel<<<sgrid, sblk, DYN_SMEM>>>(seq + (size_t)t * B_SZ * FEAT, FEAT,
                                                    h0[t & 1], 544, W0h, b0p, c0, h0[(t + 1) & 1]);
        lstm_step_kernel<<<sgrid, sblk, DYN_SMEM>>>(h0[(t + 1) & 1], HID,
                                                    h1[t & 1], 1024, W1h, b1p, c1, h1[(t + 1) & 1]);
    }

    // y0 = h1_final @ dec_w^T + dec_b   (TSTEPS even -> final parity 0)
    dec_out_kernel<<<128, 256>>>(h1[0], yb, dec_b, -1);

    for (int s = 0; s < NSTEPS; s++) {
        lstm_step_kernel<<<sgrid, sblk, DYN_SMEM>>>(yb, FEAT,
                                                    h0[s & 1], 544, W0h, b0p, c0, h0[(s + 1) & 1]);
        lstm_step_kernel<<<sgrid, sblk, DYN_SMEM>>>(h0[(s + 1) & 1], HID,
                                                    h1[s & 1], 1024, W1h, b1p, c1, h1[(s + 1) & 1]);
        dec_out_kernel<<<128, 256>>>(h1[(s + 1) & 1], yb, dec_b, s);
    }

    deconv_kernel<<<B_SZ, 64>>>(deconvw, (float*)d_out);
}

// round 13
// speedup vs baseline: 1.6286x; 1.2636x over previous
#include <cuda_runtime.h>
#include <cuda_fp16.h>
#include <cstdint>

#define B_SZ   1024
#define HID    512
#define FEAT   32
#define CIN    4
#define KCONV  30
#define STRIDEC 6
#define LIN    924
#define TSTEPS 150
#define KDD    40
#define NSTEPS 10
#define G4     2048          // 4*HID
#define BH     (B_SZ*HID)    // 524288

// tile: 128 batch rows x 64 packed gate rows; 2 CTAs/SM
#define TM 128
#define TN 64
#define TSTRIDE 40                           // halves per 32-k row (80B)
#define A_HALVES (TM * TSTRIDE)              // 5120
#define B_HALVES (TN * TSTRIDE)              // 2560
#define STAGE_HALVES (A_HALVES + B_HALVES)   // 7680
#define DYN_SMEM (2 * 2 * STAGE_HALVES * 2)  // 2 halves x 2 stages x 2B = 61440

// ---------------- device scratch (static; no allocations) ----------------
__device__ __half g_seq[TSTEPS * B_SZ * FEAT];  // conv output (fp16), [t][b][f]
__device__ __half g_W0h[G4 * 544];              // packed+permuted [Wih0|Whh0], fp16
__device__ __half g_W1h[G4 * 1024];             // packed+permuted [Wih1|Whh1], fp16
__device__ float  g_b0p[G4];
__device__ float  g_b1p[G4];
__device__ __half g_h[4 * BH];                  // h0[0],h0[1],h1[0],h1[1] (fp16)
__device__ float  g_c[2 * BH];                  // c0, c1 (fp32)
__device__ __half g_y[B_SZ * FEAT];             // decoder output (GEMM operand, fp16)
__device__ float  g_fut[NSTEPS * B_SZ * FEAT];  // full-precision decoder outputs [s][b][f]
__device__ float  g_decwT[HID * FEAT];          // dec_w transposed [j][f]

// ---------------- helpers ----------------
__device__ __forceinline__ uint32_t smem_u32(const void* p) {
    uint32_t a;
    asm("{ .reg .u64 t; cvta.to.shared.u64 t, %1; cvt.u32.u64 %0, t; }" : "=r"(a) : "l"(p));
    return a;
}
__device__ __forceinline__ void mma_f16(float* d, const unsigned* a, const unsigned* b) {
    asm volatile(
        "mma.sync.aligned.m16n8k16.row.col.f32.f16.f16.f32 "
        "{%0,%1,%2,%3}, {%4,%5,%6,%7}, {%8,%9}, {%0,%1,%2,%3};"
        : "+f"(d[0]), "+f"(d[1]), "+f"(d[2]), "+f"(d[3])
        : "r"(a[0]), "r"(a[1]), "r"(a[2]), "r"(a[3]), "r"(b[0]), "r"(b[1]));
}
__device__ __forceinline__ void ldsm_x4(unsigned* r, uint32_t addr) {
    asm volatile("ldmatrix.sync.aligned.m8n8.x4.shared.b16 {%0,%1,%2,%3}, [%4];"
        : "=r"(r[0]), "=r"(r[1]), "=r"(r[2]), "=r"(r[3]) : "r"(addr));
}
#define CP_ASYNC16(sa, gp) \
    asm volatile("cp.async.cg.shared.global [%0], [%1], 16;" :: "r"(sa), "l"(gp))
#define CP_COMMIT() asm volatile("cp.async.commit_group;" ::: "memory")
#define CP_WAIT1()  asm volatile("cp.async.wait_group 1;" ::: "memory")
#define CP_WAIT0()  asm volatile("cp.async.wait_group 0;" ::: "memory")
#define BARH(h) asm volatile("bar.sync %0, 128;" :: "r"(1 + (h)) : "memory")

// ---------------- fused setup: zero state + pack weights (one launch) ----------------
// 64-row gate blocks: packed row p -> blk = p>>6, gate = (p>>4)&3, u = p&15,
// original g = gate*512 + blk*16 + u  (16 units per 64-row block; a 64-row
// tile holds all four gates of its 16 units).
__global__ void setup_kernel(const float* __restrict__ Wih0, const float* __restrict__ Whh0,
                             const float* __restrict__ bih0, const float* __restrict__ bhh0,
                             const float* __restrict__ Wih1, const float* __restrict__ Whh1,
                             const float* __restrict__ bih1, const float* __restrict__ bhh1,
                             const float* __restrict__ dec_w) {
    long i = (long)blockIdx.x * blockDim.x + threadIdx.x;
    if (i < 2L * BH) { g_c[i] = 0.f; return; }
    long j = i - 2L * BH;
    if (j < 4L * BH) { g_h[j] = __float2half(0.f); return; }
    long j2 = j - 4L * BH;
    if (j2 < (long)G4 * 544) {
        int p = (int)(j2 / 544), k = (int)(j2 - (long)p * 544);
        int blk = p >> 6, gt = (p >> 4) & 3, u = p & 15;
        int g = gt * HID + blk * 16 + u;
        float v = (k < FEAT) ? Wih0[g * FEAT + k] : Whh0[g * HID + (k - FEAT)];
        g_W0h[j2] = __float2half(v);
        if (k == 0) g_b0p[p] = bih0[g] + bhh0[g];
        return;
    }
    long k2 = j2 - (long)G4 * 544;
    if (k2 < (long)G4 * 1024) {
        int p = (int)(k2 >> 10), k = (int)(k2 & 1023);
        int blk = p >> 6, gt = (p >> 4) & 3, u = p & 15;
        int g = gt * HID + blk * 16 + u;
        float v = (k < HID) ? Wih1[g * HID + k] : Whh1[g * HID + (k - HID)];
        g_W1h[k2] = __float2half(v);
        if (k == 0) g_b1p[p] = bih1[g] + bhh1[g];
        return;
    }
    long k3 = k2 - (long)G4 * 1024;
    if (k3 < (long)HID * FEAT) {
        int jj = (int)(k3 >> 5), f = (int)(k3 & 31);
        g_decwT[jj * FEAT + f] = dec_w[f * HID + jj];
    }
}
#define SETUP_ITEMS (2L * BH + 4L * BH + (long)G4 * 544 + (long)G4 * 1024 + (long)HID * FEAT)

// ---------------- encoder conv: [B,4,924] -> seq[t][b][f], relu, fp16 ------
__global__ void conv_kernel(const float* __restrict__ x,
                            const float* __restrict__ w,
                            const float* __restrict__ bias) {
    __shared__ float xs[CIN * LIN];
    __shared__ float ws[FEAT * CIN * KCONV];
    __shared__ float bs[FEAT];
    int b = blockIdx.x;
    for (int i = threadIdx.x; i < CIN * LIN; i += blockDim.x) xs[i] = x[b * CIN * LIN + i];
    for (int i = threadIdx.x; i < FEAT * CIN * KCONV; i += blockDim.x) ws[i] = w[i];
    if (threadIdx.x < FEAT) bs[threadIdx.x] = bias[threadIdx.x];
    __syncthreads();
    for (int o = threadIdx.x; o < FEAT * TSTEPS; o += blockDim.x) {
        int f = o / TSTEPS, t = o % TSTEPS;
        float acc = bs[f];
        #pragma unroll
        for (int c = 0; c < CIN; c++) {
            const float* xr = xs + c * LIN + t * STRIDEC;
            const float* wr = ws + (f * CIN + c) * KCONV;
            #pragma unroll
            for (int k = 0; k < KCONV; k++) acc += xr[k] * wr[k];
        }
        g_seq[(t * B_SZ + b) * FEAT + f] = __float2half(fmaxf(acc, 0.f));
    }
}

// ---------------- split-K fused LSTM step (fp16 mma, 128x64 tile, 2 CTAs/SM) ----
// grid (32 gate-tiles, 8 batch-tiles). 8 warps: half = warp>>2 owns k-tiles
// kt ≡ half (mod 2); per half a 2x2 grid of 64x32 warp tiles. cp.async double
// buffer per half, ldmatrix b16 loads, fp32 smem reduction + fused cell update.
__global__ void __launch_bounds__(256, 2)
lstm_step_kernel(const __half* __restrict__ x1, int w1,
                 const __half* __restrict__ h_in, int K,
                 const __half* __restrict__ Wp, const float* __restrict__ bp,
                 float* __restrict__ c_state, __half* __restrict__ h_out) {
    extern __shared__ __half smem[];
    const int tid  = threadIdx.x;
    const int lane = tid & 31;
    const int warp = tid >> 5;
    const int half = warp >> 2;
    const int wl   = warp & 3;
    const int wm   = wl >> 1;      // 0..1 : 64-row band
    const int wn   = wl & 1;       // 0..1 : 32-col band
    const int t128 = tid & 127;
    const int bN = blockIdx.x, bM = blockIdx.y;
    const int NT = K >> 5;

    __half* hbase = smem + half * (2 * STAGE_HALVES);   // per-half: 2 stages

    // ldmatrix lane addressing (b16, x4) — proven mapping from R11
    const int rowA = (lane & 7) + ((lane >> 3) & 1) * 8;
    const int colA = (lane >> 4) * 8;
    const int rowB = (lane & 7) + ((lane >> 4) ? 8 : 0);
    const int colB = ((lane >> 3) & 1) * 8;

    float acc[4][4][4];
    #pragma unroll
    for (int a = 0; a < 4; a++)
        #pragma unroll
        for (int b = 0; b < 4; b++)
            #pragma unroll
            for (int c = 0; c < 4; c++) acc[a][b][c] = 0.f;

    auto prefetch = [&](int kt, int s) {
        __half* As = hbase + s * STAGE_HALVES;
        __half* Bs = As + A_HALVES;
        uint32_t a_s = smem_u32(As), b_s = smem_u32(Bs);
        const int k0 = kt * 32;
        // A: 128 rows x 32 halves = 512 x 16B chunks
        #pragma unroll
        for (int i = 0; i < 4; i++) {
            int chunk = t128 + i * 128;
            int row = chunk >> 2, c8 = (chunk & 3) * 8;
            const __half* src = (k0 < w1)
                ? x1 + (size_t)(bM * TM + row) * w1 + k0 + c8
                : h_in + (size_t)(bM * TM + row) * HID + (k0 - w1) + c8;
            CP_ASYNC16(a_s + (uint32_t)(row * TSTRIDE + c8) * 2u, src);
        }
        // B: 64 rows x 32 halves = 256 x 16B chunks
        #pragma unroll
        for (int i = 0; i < 2; i++) {
            int chunk = t128 + i * 128;
            int row = chunk >> 2, c8 = (chunk & 3) * 8;
            CP_ASYNC16(b_s + (uint32_t)(row * TSTRIDE + c8) * 2u,
                       Wp + (size_t)(bN * TN + row) * K + k0 + c8);
        }
    };

    auto compute = [&](int s) {
        const __half* As = hbase + s * STAGE_HALVES;
        const __half* Bs = As + A_HALVES;
        const uint32_t a_base = smem_u32(As)
            + (uint32_t)(((wm * 64 + rowA) * TSTRIDE + colA) * 2);
        const uint32_t b_base = smem_u32(Bs)
            + (uint32_t)(((wn * 32 + rowB) * TSTRIDE + colB) * 2);
        #pragma unroll
        for (int kk = 0; kk < 2; kk++) {   // two k16 slices per 32-K tile
            unsigned af[4][4];
            #pragma unroll
            for (int mt = 0; mt < 4; mt++)
                ldsm_x4(af[mt], a_base + (uint32_t)((mt * 16 * TSTRIDE + kk * 16) * 2));
            unsigned bq[2][4];
            #pragma unroll
            for (int bi = 0; bi < 2; bi++)   // 2 x (16 n-rows)
                ldsm_x4(bq[bi], b_base + (uint32_t)((bi * 16 * TSTRIDE + kk * 16) * 2));
            #pragma unroll
            for (int mt = 0; mt < 4; mt++)
                #pragma unroll
                for (int bi = 0; bi < 2; bi++) {
                    mma_f16(acc[mt][2 * bi],     af[mt], &bq[bi][0]);
                    mma_f16(acc[mt][2 * bi + 1], af[mt], &bq[bi][2]);
                }
        }
    };

    // per-half pipelined mainloop over k-tiles kt = half, half+2, ...
    prefetch(half, 0);
    CP_COMMIT();
    if (half + 2 < NT) prefetch(half + 2, 1);
    CP_COMMIT();
    int buf = 0;
    for (int kt = half; kt < NT; kt += 2) {
        if (kt + 2 < NT) { CP_WAIT1(); } else { CP_WAIT0(); }
        BARH(half);
        compute(buf);
        BARH(half);
        if (kt + 4 < NT) prefetch(kt + 4, buf);
        CP_COMMIT();
        buf ^= 1;
    }

    // ---- cross-half reduction into gs (fp32, stride 68), then cell update ----
    __syncthreads();
    float* gs = (float*)smem;
    if (half == 1) {
        #pragma unroll
        for (int mt = 0; mt < 4; mt++)
            #pragma unroll
            for (int nt = 0; nt < 4; nt++) {
                int r0 = wm * 64 + mt * 16 + (lane >> 2);
                int c0 = wn * 32 + nt * 8 + (lane & 3) * 2;
                gs[r0 * 68 + c0]           = acc[mt][nt][0];
                gs[r0 * 68 + c0 + 1]       = acc[mt][nt][1];
                gs[(r0 + 8) * 68 + c0]     = acc[mt][nt][2];
                gs[(r0 + 8) * 68 + c0 + 1] = acc[mt][nt][3];
            }
    }
    __syncthreads();
    if (half == 0) {
        #pragma unroll
        for (int mt = 0; mt < 4; mt++)
            #pragma unroll
            for (int nt = 0; nt < 4; nt++) {
                int r0 = wm * 64 + mt * 16 + (lane >> 2);
                int c0 = wn * 32 + nt * 8 + (lane & 3) * 2;
                gs[r0 * 68 + c0]           += acc[mt][nt][0];
                gs[r0 * 68 + c0 + 1]       += acc[mt][nt][1];
                gs[(r0 + 8) * 68 + c0]     += acc[mt][nt][2];
                gs[(r0 + 8) * 68 + c0 + 1] += acc[mt][nt][3];
            }
    }
    __syncthreads();

    {
        int u  = tid & 15;          // unit within 16-unit block
        int r0 = tid >> 4;          // 0..15 batch-row group
        float bi  = bp[bN * 64 + u];
        float bf_ = bp[bN * 64 + 16 + u];
        float bg  = bp[bN * 64 + 32 + u];
        float bo  = bp[bN * 64 + 48 + u];
        int j = bN * 16 + u;        // hidden unit index
        #pragma unroll
        for (int i = 0; i < 8; i++) {
            int bl = r0 + i * 16;
            int bglob = bM * TM + bl;
            float gi = gs[bl * 68 + u] + bi;
            float gf = gs[bl * 68 + 16 + u] + bf_;
            float gg = gs[bl * 68 + 32 + u] + bg;
            float go = gs[bl * 68 + 48 + u] + bo;
            float iv = 1.f / (1.f + __expf(-gi));
            float fv = 1.f / (1.f + __expf(-gf));
            float gv = tanhf(gg);
            float ov = 1.f / (1.f + __expf(-go));
            int idx = bglob * HID + j;
            float cn = fv * c_state[idx] + iv * gv;
            c_state[idx] = cn;
            h_out[idx] = __float2half(ov * tanhf(cn));   // GEMM operand (fp16)
        }
    }
}

// ---------------- decoder projection: y = h @ dec_w^T + dec_b ----------------
__global__ void dec_out_kernel(const __half* __restrict__ h, __half* __restrict__ y,
                               const float* __restrict__ dec_b, int slot) {
    int g = blockIdx.x * blockDim.x + threadIdx.x;  // 32768
    int b = g >> 5, f = g & 31;
    float acc = dec_b[f];
    const __half* hr = h + (size_t)b * HID;
    #pragma unroll 8
    for (int j = 0; j < HID; j++) acc += __half2float(hr[j]) * g_decwT[j * FEAT + f];
    y[b * FEAT + f] = __float2half(acc);            // GEMM operand (fp16)
    if (slot >= 0) g_fut[(slot * B_SZ + b) * FEAT + f] = acc;  // full precision for output
}

// ---------------- conv transpose: fut[b,f,10] * w[f,1,40] -> out[b,1,49] ----------------
__global__ void deconv_kernel(const float* __restrict__ dw, float* __restrict__ out) {
    __shared__ float futb[NSTEPS * FEAT];
    __shared__ float dws[FEAT * KDD];
    int b = blockIdx.x;
    for (int i = threadIdx.x; i < NSTEPS * FEAT; i += blockDim.x) {
        int t = i >> 5, f = i & 31;
        futb[i] = g_fut[(t * B_SZ + b) * FEAT + f];
    }
    for (int i = threadIdx.x; i < FEAT * KDD; i += blockDim.x) dws[i] = dw[i];
    __syncthreads();
    int jj = threadIdx.x;
    if (jj < NSTEPS + KDD - 1) {
        float acc = 0.f;
        #pragma unroll
        for (int t = 0; t < NSTEPS; t++) {
            int k = jj - t;
            if (k >= 0 && k < KDD) {
                #pragma unroll
                for (int f = 0; f < FEAT; f++) acc += futb[t * FEAT + f] * dws[f * KDD + k];
            }
        }
        out[b * (NSTEPS + KDD - 1) + jj] = acc;
    }
}

// ---------------- host ----------------
extern "C" void kernel_launch(void* const* d_in, const int* in_sizes, int n_in,
                              void* d_out, int out_size) {
    const float* x       = (const float*)d_in[0];
    const float* conv_w  = (const float*)d_in[1];
    const float* conv_b  = (const float*)d_in[2];
    const float* Wih0    = (const float*)d_in[3];
    const float* Whh0    = (const float*)d_in[4];
    const float* bih0    = (const float*)d_in[5];
    const float* bhh0    = (const float*)d_in[6];
    const float* Wih1    = (const float*)d_in[7];
    const float* Whh1    = (const float*)d_in[8];
    const float* bih1    = (const float*)d_in[9];
    const float* bhh1    = (const float*)d_in[10];
    const float* dec_w   = (const float*)d_in[11];
    const float* dec_b   = (const float*)d_in[12];
    const float* deconvw = (const float*)d_in[13];

    cudaFuncSetAttribute(lstm_step_kernel,
                         cudaFuncAttributeMaxDynamicSharedMemorySize, DYN_SMEM);

    __half *seq, *hbuf, *yb, *W0h, *W1h;
    float *cbuf, *b0p, *b1p;
    cudaGetSymbolAddress((void**)&seq,  g_seq);
    cudaGetSymbolAddress((void**)&hbuf, g_h);
    cudaGetSymbolAddress((void**)&cbuf, g_c);
    cudaGetSymbolAddress((void**)&yb,   g_y);
    cudaGetSymbolAddress((void**)&W0h,  g_W0h);
    cudaGetSymbolAddress((void**)&W1h,  g_W1h);
    cudaGetSymbolAddress((void**)&b0p,  g_b0p);
    cudaGetSymbolAddress((void**)&b1p,  g_b1p);

    __half* h0[2] = { hbuf,          hbuf + BH };
    __half* h1[2] = { hbuf + 2 * BH, hbuf + 3 * BH };
    float*  c0    = cbuf;
    float*  c1    = cbuf + BH;

    // launch order keeps the K=1024 step at harness index 3 (= ncu -s 5 window)
    setup_kernel<<<(int)((SETUP_ITEMS + 255) / 256), 256>>>(Wih0, Whh0, bih0, bhh0,
                                                            Wih1, Whh1, bih1, bhh1, dec_w);
    conv_kernel<<<B_SZ, 256>>>(x, conv_w, conv_b);

    dim3 sgrid(G4 / TN, B_SZ / TM);   // (32, 8)
    dim3 sblk(256);
    for (int t = 0; t < TSTEPS; t++) {
        lstm_step_kernel<<<sgrid, sblk, DYN_SMEM>>>(seq + (size_t)t * B_SZ * FEAT, FEAT,
                                                    h0[t & 1], 544, W0h, b0p, c0, h0[(t + 1) & 1]);
        lstm_step_kernel<<<sgrid, sblk, DYN_SMEM>>>(h0[(t + 1) & 1], HID,
                                                    h1[t & 1], 1024, W1h, b1p, c1, h1[(t + 1) & 1]);
    }

    // y0 = h1_final @ dec_w^T + dec_b   (TSTEPS even -> final parity 0)
    dec_out_kernel<<<128, 256>>>(h1[0], yb, dec_b, -1);

    for (int s = 0; s < NSTEPS; s++) {
        lstm_step_kernel<<<sgrid, sblk, DYN_SMEM>>>(yb, FEAT,
                                                    h0[s & 1], 544, W0h, b0p, c0, h0[(s + 1) & 1]);
        lstm_step_kernel<<<sgrid, sblk, DYN_SMEM>>>(h0[(s + 1) & 1], HID,
                                                    h1[s & 1], 1024, W1h, b1p, c1, h1[(s + 1) & 1]);
        dec_out_kernel<<<128, 256>>>(h1[(s + 1) & 1], yb, dec_b, s);
    }

    deconv_kernel<<<B_SZ, 64>>>(deconvw, (float*)d_out);
}